// round 15
// baseline (speedup 1.0000x reference)
#include <cuda_runtime.h>
#include <cuda_fp16.h>
#include <math.h>
#include <stdint.h>

// ---------------------------------------------------------------------------
// Shapes: x (N=2, T=2048, C=512), H=8, hd=64, WIN=63, LEFT=31, hid=2048
// ---------------------------------------------------------------------------
#define C_DIM   512
#define HID_DIM 2048
#define QKV_DIM 1536
#define HEAD_D  64
#define WIN     63
#define LEFT    31
#define M_ROWS  4096

// fp16 weight buffer offsets (halves)
#define W_QKV  0
#define W_PROJ 786432
#define W_FC1  1048576
#define W_FC2  2097152
#define W_TOT  3145728

// flash-attention tiling
#define FA_TOK  128
#define FA_SPAN 192
#define FA_REAL (FA_TOK + WIN - 1)  // 190
#define FA_STR  72

// ---------------------------------------------------------------------------
// Scratch
// ---------------------------------------------------------------------------
__device__ __half g_h16  [M_ROWS * C_DIM];
__device__ __half g_qkv16[M_ROWS * QKV_DIM];
__device__ __half g_att16[M_ROWS * C_DIM];
__device__ float  g_x2   [M_ROWS * C_DIM];
__device__ __half g_m1h  [M_ROWS * HID_DIM];
__device__ __half g_w16  [W_TOT];

// ---------------------------------------------------------------------------
// PTX helpers
// ---------------------------------------------------------------------------
__device__ __forceinline__ void cp_async16_s(uint32_t s, const void* g) {
    asm volatile("cp.async.cg.shared.global [%0], [%1], 16;\n" :: "r"(s), "l"(g));
}
__device__ __forceinline__ void ldsm4(uint32_t& r0, uint32_t& r1,
                                      uint32_t& r2, uint32_t& r3, uint32_t addr) {
    asm volatile("ldmatrix.sync.aligned.m8n8.x4.shared.b16 {%0,%1,%2,%3}, [%4];"
        : "=r"(r0), "=r"(r1), "=r"(r2), "=r"(r3) : "r"(addr));
}
__device__ __forceinline__ void ldsm4t(uint32_t& r0, uint32_t& r1,
                                       uint32_t& r2, uint32_t& r3, uint32_t addr) {
    asm volatile("ldmatrix.sync.aligned.m8n8.x4.trans.shared.b16 {%0,%1,%2,%3}, [%4];"
        : "=r"(r0), "=r"(r1), "=r"(r2), "=r"(r3) : "r"(addr));
}
__device__ __forceinline__ void mma_f16(float* c, const uint32_t* a, const uint32_t* b) {
    asm volatile(
        "mma.sync.aligned.m16n8k16.row.col.f32.f16.f16.f32 "
        "{%0,%1,%2,%3}, {%4,%5,%6,%7}, {%8,%9}, {%0,%1,%2,%3};\n"
        : "+f"(c[0]), "+f"(c[1]), "+f"(c[2]), "+f"(c[3])
        : "r"(a[0]), "r"(a[1]), "r"(a[2]), "r"(a[3]), "r"(b[0]), "r"(b[1]));
}
__device__ __forceinline__ uint32_t packh2(float a, float b) {
    __half2 h = __floats2half2_rn(a, b);
    return *reinterpret_cast<uint32_t*>(&h);
}

// ---------------------------------------------------------------------------
// prep: fused weight fp32->fp16 conversion (blocks 0..6143) + LN1 (rest)
// ---------------------------------------------------------------------------
__global__ __launch_bounds__(128) void prep(
    const float* __restrict__ w0, const float* __restrict__ w1,
    const float* __restrict__ w2, const float* __restrict__ w3,
    __half* __restrict__ wout,
    const float* __restrict__ x, const float* __restrict__ lw,
    const float* __restrict__ lb, __half* __restrict__ hout)
{
    if (blockIdx.x < 6144) {
        int i = blockIdx.x * 128 + threadIdx.x;
        const float* src; int off;
        if (i < 196608)      { src = w0; off = i; }
        else if (i < 262144) { src = w1; off = i - 196608; }
        else if (i < 524288) { src = w2; off = i - 262144; }
        else                 { src = w3; off = i - 524288; }
        float4 v = ((const float4*)src)[off];
        ((__half2*)wout)[2 * i]     = __floats2half2_rn(v.x, v.y);
        ((__half2*)wout)[2 * i + 1] = __floats2half2_rn(v.z, v.w);
        return;
    }
    int row = blockIdx.x - 6144;
    int tid = threadIdx.x;
    const float4* xr = (const float4*)(x + (size_t)row * C_DIM);
    float4 v = xr[tid];
    float s  = v.x + v.y + v.z + v.w;
    float sq = v.x*v.x + v.y*v.y + v.z*v.z + v.w*v.w;
    #pragma unroll
    for (int o = 16; o > 0; o >>= 1) {
        s  += __shfl_xor_sync(0xffffffffu, s,  o);
        sq += __shfl_xor_sync(0xffffffffu, sq, o);
    }
    __shared__ float ss[4], ssq[4];
    if ((tid & 31) == 0) { ss[tid >> 5] = s; ssq[tid >> 5] = sq; }
    __syncthreads();
    s  = ss[0]  + ss[1]  + ss[2]  + ss[3];
    sq = ssq[0] + ssq[1] + ssq[2] + ssq[3];
    float mu  = s * (1.0f / C_DIM);
    float var = sq * (1.0f / C_DIM) - mu * mu;
    float inv = rsqrtf(var + 1e-5f);
    float4 wv = ((const float4*)lw)[tid];
    float4 bv = ((const float4*)lb)[tid];
    float o0 = (v.x - mu) * inv * wv.x + bv.x;
    float o1 = (v.y - mu) * inv * wv.y + bv.y;
    float o2 = (v.z - mu) * inv * wv.z + bv.z;
    float o3 = (v.w - mu) * inv * wv.w + bv.w;
    __half2* po = (__half2*)(hout + (size_t)row * C_DIM);
    po[tid * 2]     = __floats2half2_rn(o0, o1);
    po[tid * 2 + 1] = __floats2half2_rn(o2, o3);
}

// ---------------------------------------------------------------------------
// LN2: fp32 in -> fp16 out
// ---------------------------------------------------------------------------
__global__ __launch_bounds__(128) void ln_kernel_h(
    const float* __restrict__ x, const float* __restrict__ w,
    const float* __restrict__ b, __half* __restrict__ out)
{
    int row = blockIdx.x;
    int tid = threadIdx.x;
    const float4* xr = (const float4*)(x + (size_t)row * C_DIM);
    float4 v = xr[tid];
    float s  = v.x + v.y + v.z + v.w;
    float sq = v.x*v.x + v.y*v.y + v.z*v.z + v.w*v.w;
    #pragma unroll
    for (int o = 16; o > 0; o >>= 1) {
        s  += __shfl_xor_sync(0xffffffffu, s,  o);
        sq += __shfl_xor_sync(0xffffffffu, sq, o);
    }
    __shared__ float ss[4], ssq[4];
    if ((tid & 31) == 0) { ss[tid >> 5] = s; ssq[tid >> 5] = sq; }
    __syncthreads();
    s  = ss[0]  + ss[1]  + ss[2]  + ss[3];
    sq = ssq[0] + ssq[1] + ssq[2] + ssq[3];
    float mu  = s * (1.0f / C_DIM);
    float var = sq * (1.0f / C_DIM) - mu * mu;
    float inv = rsqrtf(var + 1e-5f);
    float4 wv = ((const float4*)w)[tid];
    float4 bv = ((const float4*)b)[tid];
    float o0 = (v.x - mu) * inv * wv.x + bv.x;
    float o1 = (v.y - mu) * inv * wv.y + bv.y;
    float o2 = (v.z - mu) * inv * wv.z + bv.z;
    float o3 = (v.w - mu) * inv * wv.w + bv.w;
    __half2* po = (__half2*)(out + (size_t)row * C_DIM);
    po[tid * 2]     = __floats2half2_rn(o0, o1);
    po[tid * 2 + 1] = __floats2half2_rn(o2, o3);
}

// ---------------------------------------------------------------------------
// HGEMM-64 (qkv, fc1): BM=64, BN=128, BK=64, 2-stage, (256,3). fp16 out.
// ---------------------------------------------------------------------------
template<bool GELU>
__global__ __launch_bounds__(256, 3) void hgemm64(
    const __half* __restrict__ A, const __half* __restrict__ B,
    const float* __restrict__ bias, __half* __restrict__ Cout,
    int M, int N, int K)
{
    constexpr int BM = 64, BK = 64;
    constexpr int SK = 72;
    constexpr int A_BYTES = BM * SK * 2;         // 9216
    constexpr int B_BYTES = 128 * SK * 2;        // 18432
    constexpr int STAGE_BYTES = A_BYTES + B_BYTES;
    constexpr int ROWSTEP = 16 * SK * 2;

    extern __shared__ __align__(16) __half hsm[];
    const uint32_t sbase = (uint32_t)__cvta_generic_to_shared(hsm);

    const int tid  = threadIdx.x;
    const int wid  = tid >> 5;
    const int lane = tid & 31;
    const int g    = lane >> 2;
    const int tg   = lane & 3;
    const int warp_m = wid & 1;
    const int warp_n = wid >> 1;

    const __half* Ab = A + (size_t)blockIdx.y * BM * K;
    const __half* Bb = B + (size_t)blockIdx.x * 128 * K;

    float acc[2][4][4];
    #pragma unroll
    for (int mt = 0; mt < 2; mt++)
        #pragma unroll
        for (int nt = 0; nt < 4; nt++)
            #pragma unroll
            for (int i = 0; i < 4; i++) acc[mt][nt][i] = 0.0f;

    const int qh = lane >> 3, rh = lane & 7;
    const uint32_t a_lane =
        (uint32_t)(((warp_m * 32 + rh + 8 * (qh & 1)) * SK + (qh >> 1) * 8) * 2);
    const uint32_t b_lane =
        (uint32_t)(((warp_n * 32 + rh + 8 * (qh & 1)) * SK + (qh >> 1) * 8) * 2)
        + A_BYTES;

    auto load_chunk = [&](int buf, int k0) {
        uint32_t base = sbase + buf * STAGE_BYTES;
        #pragma unroll
        for (int it = 0; it < 2; ++it) {
            int i = tid + it * 256;
            int r = i >> 3, seg = i & 7;
            uint32_t so = (uint32_t)(r * SK + seg * 8) * 2;
            cp_async16_s(base + so, Ab + (size_t)r * K + k0 + seg * 8);
        }
        #pragma unroll
        for (int it = 0; it < 4; ++it) {
            int i = tid + it * 256;
            int r = i >> 3, seg = i & 7;
            uint32_t so = (uint32_t)(r * SK + seg * 8) * 2;
            cp_async16_s(base + A_BYTES + so, Bb + (size_t)r * K + k0 + seg * 8);
        }
    };

    const int nch = K / BK;
    load_chunk(0, 0);
    asm volatile("cp.async.commit_group;");

    for (int c = 0; c < nch; ++c) {
        asm volatile("cp.async.wait_group 0;");
        __syncthreads();

        if (c + 1 < nch) {
            load_chunk((c + 1) & 1, (c + 1) * BK);
            asm volatile("cp.async.commit_group;");
        }

        const uint32_t st = sbase + (c & 1) * STAGE_BYTES;
        #pragma unroll
        for (int ks = 0; ks < 4; ++ks) {
            uint32_t aw[2][4], bw[4][2];
            #pragma unroll
            for (int nb = 0; nb < 2; ++nb) {
                uint32_t x0, x1, x2, x3;
                ldsm4(x0, x1, x2, x3, st + b_lane + nb * ROWSTEP + ks * 32);
                bw[nb * 2][0] = x0; bw[nb * 2 + 1][0] = x1;
                bw[nb * 2][1] = x2; bw[nb * 2 + 1][1] = x3;
            }
            #pragma unroll
            for (int mt = 0; mt < 2; ++mt)
                ldsm4(aw[mt][0], aw[mt][1], aw[mt][2], aw[mt][3],
                      st + a_lane + mt * ROWSTEP + ks * 32);
            #pragma unroll
            for (int mt = 0; mt < 2; ++mt)
                #pragma unroll
                for (int nt = 0; nt < 4; ++nt)
                    mma_f16(acc[mt][nt], aw[mt], bw[nt]);
        }
    }

    const int row_base = blockIdx.y * BM + warp_m * 32;
    const int col_base = blockIdx.x * 128 + warp_n * 32;
    #pragma unroll
    for (int mt = 0; mt < 2; ++mt) {
        #pragma unroll
        for (int nt = 0; nt < 4; ++nt) {
            int r0 = row_base + mt * 16 + g;
            int c0 = col_base + nt * 8 + 2 * tg;
            float b0 = bias[c0], b1 = bias[c0 + 1];
            #pragma unroll
            for (int hh = 0; hh < 2; ++hh) {
                int r = r0 + hh * 8;
                float v0 = acc[mt][nt][hh * 2 + 0] + b0;
                float v1 = acc[mt][nt][hh * 2 + 1] + b1;
                if (GELU) {
                    v0 = 0.5f * v0 * (1.0f + erff(v0 * 0.70710678118654752f));
                    v1 = 0.5f * v1 * (1.0f + erff(v1 * 0.70710678118654752f));
                }
                *(__half2*)(Cout + (size_t)r * N + c0) = __floats2half2_rn(v0, v1);
            }
        }
    }
}

// ---------------------------------------------------------------------------
// HGEMM-32 (proj, fc2): BM=32, BN=128, BK=64, 2-stage, (256,4), MT=1.
// Epilogue: out(fp32) = acc + bias + res.  grid (N/128, M/32) = 512 blocks.
// ---------------------------------------------------------------------------
__global__ __launch_bounds__(256, 4) void hgemm32(
    const __half* __restrict__ A, const __half* __restrict__ B,
    const float* __restrict__ bias, const float* __restrict__ res,
    float* __restrict__ Cout, int M, int N, int K)
{
    constexpr int BM = 32, BK = 64;
    constexpr int SK = 72;
    constexpr int A_BYTES = BM * SK * 2;         // 4608
    constexpr int B_BYTES = 128 * SK * 2;        // 18432
    constexpr int STAGE_BYTES = A_BYTES + B_BYTES;
    constexpr int ROWSTEP = 16 * SK * 2;

    extern __shared__ __align__(16) __half hsm[];
    const uint32_t sbase = (uint32_t)__cvta_generic_to_shared(hsm);

    const int tid  = threadIdx.x;
    const int wid  = tid >> 5;
    const int lane = tid & 31;
    const int g    = lane >> 2;
    const int tg   = lane & 3;
    const int warp_m = wid & 1;      // 16 rows each
    const int warp_n = wid >> 1;     // 32 cols each

    const __half* Ab = A + (size_t)blockIdx.y * BM * K;
    const __half* Bb = B + (size_t)blockIdx.x * 128 * K;

    float acc[4][4];
    #pragma unroll
    for (int nt = 0; nt < 4; nt++)
        #pragma unroll
        for (int i = 0; i < 4; i++) acc[nt][i] = 0.0f;

    const int qh = lane >> 3, rh = lane & 7;
    const uint32_t a_lane =
        (uint32_t)(((warp_m * 16 + rh + 8 * (qh & 1)) * SK + (qh >> 1) * 8) * 2);
    const uint32_t b_lane =
        (uint32_t)(((warp_n * 32 + rh + 8 * (qh & 1)) * SK + (qh >> 1) * 8) * 2)
        + A_BYTES;

    // per chunk: A 32 rows x 8 segs = 256 (1/thread); B 128 rows = 1024 (4/thread)
    auto load_chunk = [&](int buf, int k0) {
        uint32_t base = sbase + buf * STAGE_BYTES;
        {
            int r = tid >> 3, seg = tid & 7;
            uint32_t so = (uint32_t)(r * SK + seg * 8) * 2;
            cp_async16_s(base + so, Ab + (size_t)r * K + k0 + seg * 8);
        }
        #pragma unroll
        for (int it = 0; it < 4; ++it) {
            int i = tid + it * 256;
            int r = i >> 3, seg = i & 7;
            uint32_t so = (uint32_t)(r * SK + seg * 8) * 2;
            cp_async16_s(base + A_BYTES + so, Bb + (size_t)r * K + k0 + seg * 8);
        }
    };

    const int nch = K / BK;
    load_chunk(0, 0);
    asm volatile("cp.async.commit_group;");

    for (int c = 0; c < nch; ++c) {
        asm volatile("cp.async.wait_group 0;");
        __syncthreads();

        if (c + 1 < nch) {
            load_chunk((c + 1) & 1, (c + 1) * BK);
            asm volatile("cp.async.commit_group;");
        }

        const uint32_t st = sbase + (c & 1) * STAGE_BYTES;
        #pragma unroll
        for (int ks = 0; ks < 4; ++ks) {
            uint32_t aw[4], bw[4][2];
            #pragma unroll
            for (int nb = 0; nb < 2; ++nb) {
                uint32_t x0, x1, x2, x3;
                ldsm4(x0, x1, x2, x3, st + b_lane + nb * ROWSTEP + ks * 32);
                bw[nb * 2][0] = x0; bw[nb * 2 + 1][0] = x1;
                bw[nb * 2][1] = x2; bw[nb * 2 + 1][1] = x3;
            }
            ldsm4(aw[0], aw[1], aw[2], aw[3], st + a_lane + ks * 32);
            #pragma unroll
            for (int nt = 0; nt < 4; ++nt)
                mma_f16(acc[nt], aw, bw[nt]);
        }
    }

    const int row_base = blockIdx.y * BM + warp_m * 16;
    const int col_base = blockIdx.x * 128 + warp_n * 32;
    #pragma unroll
    for (int nt = 0; nt < 4; ++nt) {
        int r0 = row_base + g;
        int c0 = col_base + nt * 8 + 2 * tg;
        float b0 = bias[c0], b1 = bias[c0 + 1];
        #pragma unroll
        for (int hh = 0; hh < 2; ++hh) {
            int r = r0 + hh * 8;
            size_t off = (size_t)r * N + c0;
            float2 rv = *(const float2*)(res + off);
            float2 ov;
            ov.x = acc[nt][hh * 2 + 0] + b0 + rv.x;
            ov.y = acc[nt][hh * 2 + 1] + b1 + rv.y;
            *(float2*)(Cout + off) = ov;
        }
    }
}

// ---------------------------------------------------------------------------
// Flash windowed attention (R10-proven)
// ---------------------------------------------------------------------------
__global__ __launch_bounds__(256, 2) void fattn_kernel(
    const __half* __restrict__ qkv, const float* __restrict__ rel_bias,
    __half* __restrict__ out, int T)
{
    const int t0 = blockIdx.x * FA_TOK;
    const int h  = blockIdx.y;
    const int n  = blockIdx.z;
    const int tid  = threadIdx.x;
    const int wid  = tid >> 5;
    const int lane = tid & 31;
    const int g    = lane >> 2;
    const int tg   = lane & 3;

    extern __shared__ __align__(16) __half fsm[];
    __half* sQ = fsm;
    __half* sK = sQ + FA_TOK * FA_STR;
    __half* sV = sK + FA_SPAN * FA_STR;
    float*  sbias = (float*)(sV + FA_SPAN * FA_STR);
    const uint32_t sQb = (uint32_t)__cvta_generic_to_shared(sQ);
    const uint32_t sKb = (uint32_t)__cvta_generic_to_shared(sK);
    const uint32_t sVb = (uint32_t)__cvta_generic_to_shared(sV);

    if (tid < WIN) sbias[tid] = rel_bias[h * WIN + tid];
    const __half2 sc8 = __floats2half2_rn(0.125f, 0.125f);
    for (int i = tid; i < FA_TOK * 8; i += 256) {
        int j = i >> 3, seg = i & 7;
        const __half2* src = (const __half2*)(qkv +
            ((size_t)n * T + t0 + j) * QKV_DIM + h * HEAD_D + seg * 8);
        __half2* dst = (__half2*)(sQ + j * FA_STR + seg * 8);
        #pragma unroll
        for (int u = 0; u < 4; ++u) dst[u] = __hmul2(src[u], sc8);
    }
    for (int i = tid; i < FA_SPAN * 8; i += 256) {
        int j = i >> 3, seg = i & 7;
        int pos = t0 - LEFT + j;
        uint4 kv = make_uint4(0, 0, 0, 0), vv = make_uint4(0, 0, 0, 0);
        if (j < FA_REAL && pos >= 0 && pos < T) {
            const __half* base = qkv + ((size_t)n * T + pos) * QKV_DIM + h * HEAD_D;
            kv = *(const uint4*)(base + C_DIM + seg * 8);
            vv = *(const uint4*)(base + 2 * C_DIM + seg * 8);
        }
        *(uint4*)(sK + j * FA_STR + seg * 8) = kv;
        *(uint4*)(sV + j * FA_STR + seg * 8) = vv;
    }
    __syncthreads();

    const int r0 = wid * 16;
    const int qh = lane >> 3, rh = lane & 7;

    float acc[10][4];
    #pragma unroll
    for (int nt = 0; nt < 10; ++nt)
        #pragma unroll
        for (int c = 0; c < 4; ++c) acc[nt][c] = 0.0f;

    const uint32_t a_off = sQb +
        (uint32_t)(((r0 + rh + 8 * (qh & 1)) * FA_STR + (qh >> 1) * 8) * 2);
    const uint32_t b_off = sKb +
        (uint32_t)(((r0 + rh + 8 * (qh & 1)) * FA_STR + (qh >> 1) * 8) * 2);

    #pragma unroll
    for (int kc = 0; kc < 4; ++kc) {
        uint32_t aq[4];
        ldsm4(aq[0], aq[1], aq[2], aq[3], a_off + kc * 32);
        #pragma unroll
        for (int jp = 0; jp < 5; ++jp) {
            uint32_t x0, x1, x2, x3;
            ldsm4(x0, x1, x2, x3, b_off + (uint32_t)(jp * 16 * FA_STR * 2) + kc * 32);
            uint32_t bf0[2] = {x0, x2}, bf1[2] = {x1, x3};
            mma_f16(acc[jp * 2],     aq, bf0);
            mma_f16(acc[jp * 2 + 1], aq, bf1);
        }
    }

    float mx0 = -1e30f, mx1 = -1e30f;
    #pragma unroll
    for (int nt = 0; nt < 10; ++nt) {
        int jb = nt * 8 + 2 * tg;
        #pragma unroll
        for (int c = 0; c < 4; ++c) {
            int rl = g + ((c >> 1) << 3);
            int w  = jb + (c & 1) - rl;
            float s;
            if (w >= 0 && w < WIN) {
                int pos = t0 + r0 + rl - LEFT + w;
                s = acc[nt][c] + sbias[w];
                if (pos < 0 || pos >= T) s -= 100.0f;
            } else {
                s = -1e30f;
            }
            acc[nt][c] = s;
            if (c < 2) mx0 = fmaxf(mx0, s); else mx1 = fmaxf(mx1, s);
        }
    }
    mx0 = fmaxf(mx0, __shfl_xor_sync(0xffffffffu, mx0, 1));
    mx0 = fmaxf(mx0, __shfl_xor_sync(0xffffffffu, mx0, 2));
    mx1 = fmaxf(mx1, __shfl_xor_sync(0xffffffffu, mx1, 1));
    mx1 = fmaxf(mx1, __shfl_xor_sync(0xffffffffu, mx1, 2));

    float sm0 = 0.0f, sm1 = 0.0f;
    #pragma unroll
    for (int nt = 0; nt < 10; ++nt) {
        float e0 = __expf(acc[nt][0] - mx0);
        float e1 = __expf(acc[nt][1] - mx0);
        float e2 = __expf(acc[nt][2] - mx1);
        float e3 = __expf(acc[nt][3] - mx1);
        acc[nt][0] = e0; acc[nt][1] = e1; acc[nt][2] = e2; acc[nt][3] = e3;
        sm0 += e0 + e1; sm1 += e2 + e3;
    }
    sm0 += __shfl_xor_sync(0xffffffffu, sm0, 1);
    sm0 += __shfl_xor_sync(0xffffffffu, sm0, 2);
    sm1 += __shfl_xor_sync(0xffffffffu, sm1, 1);
    sm1 += __shfl_xor_sync(0xffffffffu, sm1, 2);
    const float rinv0 = 1.0f / sm0;
    const float rinv1 = 1.0f / sm1;

    float oacc[8][4];
    #pragma unroll
    for (int nt = 0; nt < 8; ++nt)
        #pragma unroll
        for (int c = 0; c < 4; ++c) oacc[nt][c] = 0.0f;

    const uint32_t v_off = sVb +
        (uint32_t)(((r0 + (lane & 15)) * FA_STR + 8 * (lane >> 4)) * 2);

    #pragma unroll
    for (int kc = 0; kc < 5; ++kc) {
        uint32_t ap[4];
        ap[0] = packh2(acc[2 * kc][0],     acc[2 * kc][1]);
        ap[1] = packh2(acc[2 * kc][2],     acc[2 * kc][3]);
        ap[2] = packh2(acc[2 * kc + 1][0], acc[2 * kc + 1][1]);
        ap[3] = packh2(acc[2 * kc + 1][2], acc[2 * kc + 1][3]);
        #pragma unroll
        for (int np = 0; np < 4; ++np) {
            uint32_t x0, x1, x2, x3;
            ldsm4t(x0, x1, x2, x3,
                   v_off + (uint32_t)(kc * 16 * FA_STR * 2) + (uint32_t)(np * 32));
            uint32_t bf0[2] = {x0, x1}, bf1[2] = {x2, x3};
            mma_f16(oacc[np * 2],     ap, bf0);
            mma_f16(oacc[np * 2 + 1], ap, bf1);
        }
    }

    __half* orow0 = out + ((size_t)n * T + t0 + r0 + g) * C_DIM + h * HEAD_D;
    __half* orow1 = orow0 + 8 * C_DIM;
    #pragma unroll
    for (int nt = 0; nt < 8; ++nt) {
        int d = nt * 8 + 2 * tg;
        *(__half2*)(orow0 + d) =
            __floats2half2_rn(oacc[nt][0] * rinv0, oacc[nt][1] * rinv0);
        *(__half2*)(orow1 + d) =
            __floats2half2_rn(oacc[nt][2] * rinv1, oacc[nt][3] * rinv1);
    }
}

// ---------------------------------------------------------------------------
// Launch
// ---------------------------------------------------------------------------
extern "C" void kernel_launch(void* const* d_in, const int* in_sizes, int n_in,
                              void* d_out, int out_size)
{
    const float* x       = (const float*)d_in[0];
    const float* norm1_w = (const float*)d_in[1];
    const float* norm1_b = (const float*)d_in[2];
    const float* qkv_w   = (const float*)d_in[3];
    const float* qkv_b   = (const float*)d_in[4];
    const float* relbias = (const float*)d_in[5];
    const float* proj_w  = (const float*)d_in[6];
    const float* proj_b  = (const float*)d_in[7];
    const float* norm2_w = (const float*)d_in[8];
    const float* norm2_b = (const float*)d_in[9];
    const float* fc1_w   = (const float*)d_in[10];
    const float* fc1_b   = (const float*)d_in[11];
    const float* fc2_w   = (const float*)d_in[12];
    const float* fc2_b   = (const float*)d_in[13];
    float* out = (float*)d_out;

    int M = in_sizes[0] / C_DIM;   // 4096
    int Nb = 2;
    int T = M / Nb;                // 2048

    __half *p_h16, *p_qkv16, *p_att16, *p_m1h, *p_w16;
    float *p_x2;
    cudaGetSymbolAddress((void**)&p_h16,   g_h16);
    cudaGetSymbolAddress((void**)&p_qkv16, g_qkv16);
    cudaGetSymbolAddress((void**)&p_att16, g_att16);
    cudaGetSymbolAddress((void**)&p_x2,    g_x2);
    cudaGetSymbolAddress((void**)&p_m1h,   g_m1h);
    cudaGetSymbolAddress((void**)&p_w16,   g_w16);

    const int FA_SMEM   = (FA_TOK + 2 * FA_SPAN) * FA_STR * 2 + 64 * 4;
    const int HG64_SMEM = 2 * (9216 + 18432);   // 55296
    const int HG32_SMEM = 2 * (4608 + 18432);   // 46080
    cudaFuncSetAttribute(fattn_kernel,
        cudaFuncAttributeMaxDynamicSharedMemorySize, FA_SMEM);
    cudaFuncSetAttribute(hgemm64<false>,
        cudaFuncAttributeMaxDynamicSharedMemorySize, HG64_SMEM);
    cudaFuncSetAttribute(hgemm64<true>,
        cudaFuncAttributeMaxDynamicSharedMemorySize, HG64_SMEM);
    cudaFuncSetAttribute(hgemm32,
        cudaFuncAttributeMaxDynamicSharedMemorySize, HG32_SMEM);

    // 0+1) fused weights->fp16 and LN1
    prep<<<6144 + M, 128>>>(qkv_w, proj_w, fc1_w, fc2_w, p_w16,
                            x, norm1_w, norm1_b, p_h16);

    // 2) qkv = h @ qkv_w^T + qkv_b  (fp16)       grid 12 x 64 = 768
    hgemm64<false><<<dim3(QKV_DIM / 128, M / 64), 256, HG64_SMEM>>>(
        p_h16, p_w16 + W_QKV, qkv_b, p_qkv16, M, QKV_DIM, C_DIM);

    // 3) flash windowed attention (fp16)
    fattn_kernel<<<dim3(T / FA_TOK, 8, Nb), 256, FA_SMEM>>>(
        p_qkv16, relbias, p_att16, T);

    // 4) x2 = att @ proj_w^T + proj_b + x  (fp32)  grid 4 x 128 = 512
    hgemm32<<<dim3(C_DIM / 128, M / 32), 256, HG32_SMEM>>>(
        p_att16, p_w16 + W_PROJ, proj_b, x, p_x2, M, C_DIM, C_DIM);

    // 5) h = LN2(x2) -> fp16
    ln_kernel_h<<<M, 128>>>(p_x2, norm2_w, norm2_b, p_h16);

    // 6) m1 = gelu(h @ fc1_w^T + fc1_b)  (fp16)   grid 16 x 64 = 1024
    hgemm64<true><<<dim3(HID_DIM / 128, M / 64), 256, HG64_SMEM>>>(
        p_h16, p_w16 + W_FC1, fc1_b, p_m1h, M, HID_DIM, C_DIM);

    // 7) out = m1 @ fc2_w^T + fc2_b + x2  (fp32)  grid 4 x 128 = 512
    hgemm32<<<dim3(C_DIM / 128, M / 32), 256, HG32_SMEM>>>(
        p_m1h, p_w16 + W_FC2, fc2_b, p_x2, out, M, C_DIM, HID_DIM);
}

// round 16
// speedup vs baseline: 1.1011x; 1.1011x over previous
#include <cuda_runtime.h>
#include <cuda_fp16.h>
#include <math.h>
#include <stdint.h>

// ---------------------------------------------------------------------------
// Shapes: x (N=2, T=2048, C=512), H=8, hd=64, WIN=63, LEFT=31, hid=2048
// ---------------------------------------------------------------------------
#define C_DIM   512
#define HID_DIM 2048
#define QKV_DIM 1536
#define HEAD_D  64
#define WIN     63
#define LEFT    31
#define M_ROWS  4096

// fp16 weight buffer offsets (halves)
#define W_QKV  0
#define W_PROJ 786432
#define W_FC1  1048576
#define W_FC2  2097152
#define W_TOT  3145728

// flash-attention tiling
#define FA_TOK  128
#define FA_SPAN 192
#define FA_REAL (FA_TOK + WIN - 1)  // 190
#define FA_STR  72

// ---------------------------------------------------------------------------
// Scratch
// ---------------------------------------------------------------------------
__device__ __half g_h16  [M_ROWS * C_DIM];
__device__ __half g_qkv16[M_ROWS * QKV_DIM];
__device__ __half g_att16[M_ROWS * C_DIM];
__device__ float  g_x2   [M_ROWS * C_DIM];
__device__ __half g_m1h  [M_ROWS * HID_DIM];
__device__ __half g_w16  [W_TOT];

// ---------------------------------------------------------------------------
// PTX helpers
// ---------------------------------------------------------------------------
__device__ __forceinline__ void cp_async16_s(uint32_t s, const void* g) {
    asm volatile("cp.async.cg.shared.global [%0], [%1], 16;\n" :: "r"(s), "l"(g));
}
__device__ __forceinline__ void ldsm4(uint32_t& r0, uint32_t& r1,
                                      uint32_t& r2, uint32_t& r3, uint32_t addr) {
    asm volatile("ldmatrix.sync.aligned.m8n8.x4.shared.b16 {%0,%1,%2,%3}, [%4];"
        : "=r"(r0), "=r"(r1), "=r"(r2), "=r"(r3) : "r"(addr));
}
__device__ __forceinline__ void ldsm4t(uint32_t& r0, uint32_t& r1,
                                       uint32_t& r2, uint32_t& r3, uint32_t addr) {
    asm volatile("ldmatrix.sync.aligned.m8n8.x4.trans.shared.b16 {%0,%1,%2,%3}, [%4];"
        : "=r"(r0), "=r"(r1), "=r"(r2), "=r"(r3) : "r"(addr));
}
__device__ __forceinline__ void mma_f16(float* c, const uint32_t* a, const uint32_t* b) {
    asm volatile(
        "mma.sync.aligned.m16n8k16.row.col.f32.f16.f16.f32 "
        "{%0,%1,%2,%3}, {%4,%5,%6,%7}, {%8,%9}, {%0,%1,%2,%3};\n"
        : "+f"(c[0]), "+f"(c[1]), "+f"(c[2]), "+f"(c[3])
        : "r"(a[0]), "r"(a[1]), "r"(a[2]), "r"(a[3]), "r"(b[0]), "r"(b[1]));
}
__device__ __forceinline__ uint32_t packh2(float a, float b) {
    __half2 h = __floats2half2_rn(a, b);
    return *reinterpret_cast<uint32_t*>(&h);
}

// ---------------------------------------------------------------------------
// Row LayerNorm helper: 128 threads (of a 256 block) handle one row.
// half = tid>>7 (0/1), tidr = tid&127. Reduction within the 4-warp half.
// ---------------------------------------------------------------------------
__device__ __forceinline__ void ln_row_2(
    const float* __restrict__ xrow, const float* __restrict__ w,
    const float* __restrict__ b, __half* __restrict__ orow,
    int tidr, int half, float* ssum, float* ssq)
{
    float4 v = ((const float4*)xrow)[tidr];
    float s  = v.x + v.y + v.z + v.w;
    float sq = v.x*v.x + v.y*v.y + v.z*v.z + v.w*v.w;
    #pragma unroll
    for (int o = 16; o > 0; o >>= 1) {
        s  += __shfl_xor_sync(0xffffffffu, s,  o);
        sq += __shfl_xor_sync(0xffffffffu, sq, o);
    }
    int w4 = (tidr >> 5) + half * 4;
    if ((tidr & 31) == 0) { ssum[w4] = s; ssq[w4] = sq; }
    __syncthreads();
    int base = half * 4;
    s  = ssum[base] + ssum[base+1] + ssum[base+2] + ssum[base+3];
    sq = ssq[base]  + ssq[base+1]  + ssq[base+2]  + ssq[base+3];
    float mu  = s * (1.0f / C_DIM);
    float var = sq * (1.0f / C_DIM) - mu * mu;
    float inv = rsqrtf(var + 1e-5f);
    float4 wv = ((const float4*)w)[tidr];
    float4 bv = ((const float4*)b)[tidr];
    float o0 = (v.x - mu) * inv * wv.x + bv.x;
    float o1 = (v.y - mu) * inv * wv.y + bv.y;
    float o2 = (v.z - mu) * inv * wv.z + bv.z;
    float o3 = (v.w - mu) * inv * wv.w + bv.w;
    __half2* po = (__half2*)orow;
    po[tidr * 2]     = __floats2half2_rn(o0, o1);
    po[tidr * 2 + 1] = __floats2half2_rn(o2, o3);
}

// ---------------------------------------------------------------------------
// prep: weights fp32->fp16 (blocks 0..3071, 256 thr) + LN1 (2 rows/block)
// ---------------------------------------------------------------------------
__global__ __launch_bounds__(256) void prep(
    const float* __restrict__ w0, const float* __restrict__ w1,
    const float* __restrict__ w2, const float* __restrict__ w3,
    __half* __restrict__ wout,
    const float* __restrict__ x, const float* __restrict__ lw,
    const float* __restrict__ lb, __half* __restrict__ hout)
{
    if (blockIdx.x < 3072) {
        int i = blockIdx.x * 256 + threadIdx.x;   // float4 idx < 786432
        const float* src; int off;
        if (i < 196608)      { src = w0; off = i; }
        else if (i < 262144) { src = w1; off = i - 196608; }
        else if (i < 524288) { src = w2; off = i - 262144; }
        else                 { src = w3; off = i - 524288; }
        float4 v = ((const float4*)src)[off];
        ((__half2*)wout)[2 * i]     = __floats2half2_rn(v.x, v.y);
        ((__half2*)wout)[2 * i + 1] = __floats2half2_rn(v.z, v.w);
        return;
    }
    __shared__ float ssum[8], ssq[8];
    int tid  = threadIdx.x;
    int half = tid >> 7;
    int tidr = tid & 127;
    int row  = (blockIdx.x - 3072) * 2 + half;
    ln_row_2(x + (size_t)row * C_DIM, lw, lb,
             hout + (size_t)row * C_DIM, tidr, half, ssum, ssq);
}

// ---------------------------------------------------------------------------
// LN2: 2 rows per 256-thread block, fp32 in -> fp16 out
// ---------------------------------------------------------------------------
__global__ __launch_bounds__(256) void ln_kernel_h(
    const float* __restrict__ x, const float* __restrict__ w,
    const float* __restrict__ b, __half* __restrict__ out)
{
    __shared__ float ssum[8], ssq[8];
    int tid  = threadIdx.x;
    int half = tid >> 7;
    int tidr = tid & 127;
    int row  = blockIdx.x * 2 + half;
    ln_row_2(x + (size_t)row * C_DIM, w, b,
             out + (size_t)row * C_DIM, tidr, half, ssum, ssq);
}

// ---------------------------------------------------------------------------
// Unified HGEMM (R14-proven): BM=64, BN=128, BK=64, 2-stage, (256,3).
// OUTH: fp16 output (else fp32). GELU on fp16 path. RES: +res (fp32 path).
// ---------------------------------------------------------------------------
template<bool OUTH, bool GELU, bool RES>
__global__ __launch_bounds__(256, 3) void hgemm64(
    const __half* __restrict__ A, const __half* __restrict__ B,
    const float* __restrict__ bias, const float* __restrict__ res,
    void* __restrict__ Cout, int M, int N, int K)
{
    constexpr int BM = 64, BK = 64;
    constexpr int SK = 72;
    constexpr int A_BYTES = BM * SK * 2;         // 9216
    constexpr int B_BYTES = 128 * SK * 2;        // 18432
    constexpr int STAGE_BYTES = A_BYTES + B_BYTES;
    constexpr int ROWSTEP = 16 * SK * 2;

    extern __shared__ __align__(16) __half hsm[];
    const uint32_t sbase = (uint32_t)__cvta_generic_to_shared(hsm);

    const int tid  = threadIdx.x;
    const int wid  = tid >> 5;
    const int lane = tid & 31;
    const int g    = lane >> 2;
    const int tg   = lane & 3;
    const int warp_m = wid & 1;      // 32 rows
    const int warp_n = wid >> 1;     // 32 cols

    const __half* Ab = A + (size_t)blockIdx.y * BM * K;
    const __half* Bb = B + (size_t)blockIdx.x * 128 * K;

    float acc[2][4][4];
    #pragma unroll
    for (int mt = 0; mt < 2; mt++)
        #pragma unroll
        for (int nt = 0; nt < 4; nt++)
            #pragma unroll
            for (int i = 0; i < 4; i++) acc[mt][nt][i] = 0.0f;

    const int qh = lane >> 3, rh = lane & 7;
    const uint32_t a_lane =
        (uint32_t)(((warp_m * 32 + rh + 8 * (qh & 1)) * SK + (qh >> 1) * 8) * 2);
    const uint32_t b_lane =
        (uint32_t)(((warp_n * 32 + rh + 8 * (qh & 1)) * SK + (qh >> 1) * 8) * 2)
        + A_BYTES;

    auto load_chunk = [&](int buf, int k0) {
        uint32_t base = sbase + buf * STAGE_BYTES;
        #pragma unroll
        for (int it = 0; it < 2; ++it) {
            int i = tid + it * 256;
            int r = i >> 3, seg = i & 7;
            uint32_t so = (uint32_t)(r * SK + seg * 8) * 2;
            cp_async16_s(base + so, Ab + (size_t)r * K + k0 + seg * 8);
        }
        #pragma unroll
        for (int it = 0; it < 4; ++it) {
            int i = tid + it * 256;
            int r = i >> 3, seg = i & 7;
            uint32_t so = (uint32_t)(r * SK + seg * 8) * 2;
            cp_async16_s(base + A_BYTES + so, Bb + (size_t)r * K + k0 + seg * 8);
        }
    };

    const int nch = K / BK;
    load_chunk(0, 0);
    asm volatile("cp.async.commit_group;");

    for (int c = 0; c < nch; ++c) {
        asm volatile("cp.async.wait_group 0;");
        __syncthreads();

        if (c + 1 < nch) {
            load_chunk((c + 1) & 1, (c + 1) * BK);
            asm volatile("cp.async.commit_group;");
        }

        const uint32_t st = sbase + (c & 1) * STAGE_BYTES;
        #pragma unroll
        for (int ks = 0; ks < 4; ++ks) {
            uint32_t aw[2][4], bw[4][2];
            #pragma unroll
            for (int nb = 0; nb < 2; ++nb) {
                uint32_t x0, x1, x2, x3;
                ldsm4(x0, x1, x2, x3, st + b_lane + nb * ROWSTEP + ks * 32);
                bw[nb * 2][0] = x0; bw[nb * 2 + 1][0] = x1;
                bw[nb * 2][1] = x2; bw[nb * 2 + 1][1] = x3;
            }
            #pragma unroll
            for (int mt = 0; mt < 2; ++mt)
                ldsm4(aw[mt][0], aw[mt][1], aw[mt][2], aw[mt][3],
                      st + a_lane + mt * ROWSTEP + ks * 32);
            #pragma unroll
            for (int mt = 0; mt < 2; ++mt)
                #pragma unroll
                for (int nt = 0; nt < 4; ++nt)
                    mma_f16(acc[mt][nt], aw[mt], bw[nt]);
        }
    }

    const int row_base = blockIdx.y * BM + warp_m * 32;
    const int col_base = blockIdx.x * 128 + warp_n * 32;
    #pragma unroll
    for (int mt = 0; mt < 2; ++mt) {
        #pragma unroll
        for (int nt = 0; nt < 4; ++nt) {
            int r0 = row_base + mt * 16 + g;
            int c0 = col_base + nt * 8 + 2 * tg;
            float b0 = bias[c0], b1 = bias[c0 + 1];
            #pragma unroll
            for (int hh = 0; hh < 2; ++hh) {
                int r = r0 + hh * 8;
                size_t off = (size_t)r * N + c0;
                float v0 = acc[mt][nt][hh * 2 + 0] + b0;
                float v1 = acc[mt][nt][hh * 2 + 1] + b1;
                if (RES) {
                    float2 rv = *(const float2*)(res + off);
                    v0 += rv.x; v1 += rv.y;
                }
                if (GELU) {
                    v0 = 0.5f * v0 * (1.0f + erff(v0 * 0.70710678118654752f));
                    v1 = 0.5f * v1 * (1.0f + erff(v1 * 0.70710678118654752f));
                }
                if (OUTH) {
                    *(__half2*)((__half*)Cout + off) = __floats2half2_rn(v0, v1);
                } else {
                    float2 ov; ov.x = v0; ov.y = v1;
                    *(float2*)((float*)Cout + off) = ov;
                }
            }
        }
    }
}

// ---------------------------------------------------------------------------
// Flash windowed attention (R10-proven)
// ---------------------------------------------------------------------------
__global__ __launch_bounds__(256, 2) void fattn_kernel(
    const __half* __restrict__ qkv, const float* __restrict__ rel_bias,
    __half* __restrict__ out, int T)
{
    const int t0 = blockIdx.x * FA_TOK;
    const int h  = blockIdx.y;
    const int n  = blockIdx.z;
    const int tid  = threadIdx.x;
    const int wid  = tid >> 5;
    const int lane = tid & 31;
    const int g    = lane >> 2;
    const int tg   = lane & 3;

    extern __shared__ __align__(16) __half fsm[];
    __half* sQ = fsm;
    __half* sK = sQ + FA_TOK * FA_STR;
    __half* sV = sK + FA_SPAN * FA_STR;
    float*  sbias = (float*)(sV + FA_SPAN * FA_STR);
    const uint32_t sQb = (uint32_t)__cvta_generic_to_shared(sQ);
    const uint32_t sKb = (uint32_t)__cvta_generic_to_shared(sK);
    const uint32_t sVb = (uint32_t)__cvta_generic_to_shared(sV);

    if (tid < WIN) sbias[tid] = rel_bias[h * WIN + tid];
    const __half2 sc8 = __floats2half2_rn(0.125f, 0.125f);
    for (int i = tid; i < FA_TOK * 8; i += 256) {
        int j = i >> 3, seg = i & 7;
        const __half2* src = (const __half2*)(qkv +
            ((size_t)n * T + t0 + j) * QKV_DIM + h * HEAD_D + seg * 8);
        __half2* dst = (__half2*)(sQ + j * FA_STR + seg * 8);
        #pragma unroll
        for (int u = 0; u < 4; ++u) dst[u] = __hmul2(src[u], sc8);
    }
    for (int i = tid; i < FA_SPAN * 8; i += 256) {
        int j = i >> 3, seg = i & 7;
        int pos = t0 - LEFT + j;
        uint4 kv = make_uint4(0, 0, 0, 0), vv = make_uint4(0, 0, 0, 0);
        if (j < FA_REAL && pos >= 0 && pos < T) {
            const __half* base = qkv + ((size_t)n * T + pos) * QKV_DIM + h * HEAD_D;
            kv = *(const uint4*)(base + C_DIM + seg * 8);
            vv = *(const uint4*)(base + 2 * C_DIM + seg * 8);
        }
        *(uint4*)(sK + j * FA_STR + seg * 8) = kv;
        *(uint4*)(sV + j * FA_STR + seg * 8) = vv;
    }
    __syncthreads();

    const int r0 = wid * 16;
    const int qh = lane >> 3, rh = lane & 7;

    float acc[10][4];
    #pragma unroll
    for (int nt = 0; nt < 10; ++nt)
        #pragma unroll
        for (int c = 0; c < 4; ++c) acc[nt][c] = 0.0f;

    const uint32_t a_off = sQb +
        (uint32_t)(((r0 + rh + 8 * (qh & 1)) * FA_STR + (qh >> 1) * 8) * 2);
    const uint32_t b_off = sKb +
        (uint32_t)(((r0 + rh + 8 * (qh & 1)) * FA_STR + (qh >> 1) * 8) * 2);

    #pragma unroll
    for (int kc = 0; kc < 4; ++kc) {
        uint32_t aq[4];
        ldsm4(aq[0], aq[1], aq[2], aq[3], a_off + kc * 32);
        #pragma unroll
        for (int jp = 0; jp < 5; ++jp) {
            uint32_t x0, x1, x2, x3;
            ldsm4(x0, x1, x2, x3, b_off + (uint32_t)(jp * 16 * FA_STR * 2) + kc * 32);
            uint32_t bf0[2] = {x0, x2}, bf1[2] = {x1, x3};
            mma_f16(acc[jp * 2],     aq, bf0);
            mma_f16(acc[jp * 2 + 1], aq, bf1);
        }
    }

    float mx0 = -1e30f, mx1 = -1e30f;
    #pragma unroll
    for (int nt = 0; nt < 10; ++nt) {
        int jb = nt * 8 + 2 * tg;
        #pragma unroll
        for (int c = 0; c < 4; ++c) {
            int rl = g + ((c >> 1) << 3);
            int w  = jb + (c & 1) - rl;
            float s;
            if (w >= 0 && w < WIN) {
                int pos = t0 + r0 + rl - LEFT + w;
                s = acc[nt][c] + sbias[w];
                if (pos < 0 || pos >= T) s -= 100.0f;
            } else {
                s = -1e30f;
            }
            acc[nt][c] = s;
            if (c < 2) mx0 = fmaxf(mx0, s); else mx1 = fmaxf(mx1, s);
        }
    }
    mx0 = fmaxf(mx0, __shfl_xor_sync(0xffffffffu, mx0, 1));
    mx0 = fmaxf(mx0, __shfl_xor_sync(0xffffffffu, mx0, 2));
    mx1 = fmaxf(mx1, __shfl_xor_sync(0xffffffffu, mx1, 1));
    mx1 = fmaxf(mx1, __shfl_xor_sync(0xffffffffu, mx1, 2));

    float sm0 = 0.0f, sm1 = 0.0f;
    #pragma unroll
    for (int nt = 0; nt < 10; ++nt) {
        float e0 = __expf(acc[nt][0] - mx0);
        float e1 = __expf(acc[nt][1] - mx0);
        float e2 = __expf(acc[nt][2] - mx1);
        float e3 = __expf(acc[nt][3] - mx1);
        acc[nt][0] = e0; acc[nt][1] = e1; acc[nt][2] = e2; acc[nt][3] = e3;
        sm0 += e0 + e1; sm1 += e2 + e3;
    }
    sm0 += __shfl_xor_sync(0xffffffffu, sm0, 1);
    sm0 += __shfl_xor_sync(0xffffffffu, sm0, 2);
    sm1 += __shfl_xor_sync(0xffffffffu, sm1, 1);
    sm1 += __shfl_xor_sync(0xffffffffu, sm1, 2);
    const float rinv0 = 1.0f / sm0;
    const float rinv1 = 1.0f / sm1;

    float oacc[8][4];
    #pragma unroll
    for (int nt = 0; nt < 8; ++nt)
        #pragma unroll
        for (int c = 0; c < 4; ++c) oacc[nt][c] = 0.0f;

    const uint32_t v_off = sVb +
        (uint32_t)(((r0 + (lane & 15)) * FA_STR + 8 * (lane >> 4)) * 2);

    #pragma unroll
    for (int kc = 0; kc < 5; ++kc) {
        uint32_t ap[4];
        ap[0] = packh2(acc[2 * kc][0],     acc[2 * kc][1]);
        ap[1] = packh2(acc[2 * kc][2],     acc[2 * kc][3]);
        ap[2] = packh2(acc[2 * kc + 1][0], acc[2 * kc + 1][1]);
        ap[3] = packh2(acc[2 * kc + 1][2], acc[2 * kc + 1][3]);
        #pragma unroll
        for (int np = 0; np < 4; ++np) {
            uint32_t x0, x1, x2, x3;
            ldsm4t(x0, x1, x2, x3,
                   v_off + (uint32_t)(kc * 16 * FA_STR * 2) + (uint32_t)(np * 32));
            uint32_t bf0[2] = {x0, x1}, bf1[2] = {x2, x3};
            mma_f16(oacc[np * 2],     ap, bf0);
            mma_f16(oacc[np * 2 + 1], ap, bf1);
        }
    }

    __half* orow0 = out + ((size_t)n * T + t0 + r0 + g) * C_DIM + h * HEAD_D;
    __half* orow1 = orow0 + 8 * C_DIM;
    #pragma unroll
    for (int nt = 0; nt < 8; ++nt) {
        int d = nt * 8 + 2 * tg;
        *(__half2*)(orow0 + d) =
            __floats2half2_rn(oacc[nt][0] * rinv0, oacc[nt][1] * rinv0);
        *(__half2*)(orow1 + d) =
            __floats2half2_rn(oacc[nt][2] * rinv1, oacc[nt][3] * rinv1);
    }
}

// ---------------------------------------------------------------------------
// Launch
// ---------------------------------------------------------------------------
extern "C" void kernel_launch(void* const* d_in, const int* in_sizes, int n_in,
                              void* d_out, int out_size)
{
    const float* x       = (const float*)d_in[0];
    const float* norm1_w = (const float*)d_in[1];
    const float* norm1_b = (const float*)d_in[2];
    const float* qkv_w   = (const float*)d_in[3];
    const float* qkv_b   = (const float*)d_in[4];
    const float* relbias = (const float*)d_in[5];
    const float* proj_w  = (const float*)d_in[6];
    const float* proj_b  = (const float*)d_in[7];
    const float* norm2_w = (const float*)d_in[8];
    const float* norm2_b = (const float*)d_in[9];
    const float* fc1_w   = (const float*)d_in[10];
    const float* fc1_b   = (const float*)d_in[11];
    const float* fc2_w   = (const float*)d_in[12];
    const float* fc2_b   = (const float*)d_in[13];
    float* out = (float*)d_out;

    int M = in_sizes[0] / C_DIM;   // 4096
    int Nb = 2;
    int T = M / Nb;                // 2048

    __half *p_h16, *p_qkv16, *p_att16, *p_m1h, *p_w16;
    float *p_x2;
    cudaGetSymbolAddress((void**)&p_h16,   g_h16);
    cudaGetSymbolAddress((void**)&p_qkv16, g_qkv16);
    cudaGetSymbolAddress((void**)&p_att16, g_att16);
    cudaGetSymbolAddress((void**)&p_x2,    g_x2);
    cudaGetSymbolAddress((void**)&p_m1h,   g_m1h);
    cudaGetSymbolAddress((void**)&p_w16,   g_w16);

    const int FA_SMEM   = (FA_TOK + 2 * FA_SPAN) * FA_STR * 2 + 64 * 4;
    const int HG64_SMEM = 2 * (9216 + 18432);  // 55296
    cudaFuncSetAttribute(fattn_kernel,
        cudaFuncAttributeMaxDynamicSharedMemorySize, FA_SMEM);
    cudaFuncSetAttribute(hgemm64<true, false, false>,
        cudaFuncAttributeMaxDynamicSharedMemorySize, HG64_SMEM);
    cudaFuncSetAttribute(hgemm64<true, true, false>,
        cudaFuncAttributeMaxDynamicSharedMemorySize, HG64_SMEM);
    cudaFuncSetAttribute(hgemm64<false, false, true>,
        cudaFuncAttributeMaxDynamicSharedMemorySize, HG64_SMEM);

    // 0+1) fused weights->fp16 (3072 blocks) and LN1 (2048 blocks, 2 rows ea)
    prep<<<3072 + M / 2, 256>>>(qkv_w, proj_w, fc1_w, fc2_w, p_w16,
                                x, norm1_w, norm1_b, p_h16);

    // 2) qkv = h @ qkv_w^T + qkv_b  (fp16)       grid 12 x 64 = 768
    hgemm64<true, false, false><<<dim3(QKV_DIM / 128, M / 64), 256, HG64_SMEM>>>(
        p_h16, p_w16 + W_QKV, qkv_b, nullptr, p_qkv16, M, QKV_DIM, C_DIM);

    // 3) flash windowed attention (fp16)
    fattn_kernel<<<dim3(T / FA_TOK, 8, Nb), 256, FA_SMEM>>>(
        p_qkv16, relbias, p_att16, T);

    // 4) x2 = att @ proj_w^T + proj_b + x  (fp32)  grid 4 x 64 = 256
    hgemm64<false, false, true><<<dim3(C_DIM / 128, M / 64), 256, HG64_SMEM>>>(
        p_att16, p_w16 + W_PROJ, proj_b, x, p_x2, M, C_DIM, C_DIM);

    // 5) h = LN2(x2) -> fp16 (2 rows per block)
    ln_kernel_h<<<M / 2, 256>>>(p_x2, norm2_w, norm2_b, p_h16);

    // 6) m1 = gelu(h @ fc1_w^T + fc1_b)  (fp16)   grid 16 x 64 = 1024
    hgemm64<true, true, false><<<dim3(HID_DIM / 128, M / 64), 256, HG64_SMEM>>>(
        p_h16, p_w16 + W_FC1, fc1_b, nullptr, p_m1h, M, HID_DIM, C_DIM);

    // 7) out = m1 @ fc2_w^T + fc2_b + x2  (fp32)  grid 4 x 64 = 256
    hgemm64<false, false, true><<<dim3(C_DIM / 128, M / 64), 256, HG64_SMEM>>>(
        p_m1h, p_w16 + W_FC2, fc2_b, p_x2, out, M, C_DIM, HID_DIM);
}